// round 12
// baseline (speedup 1.0000x reference)
#include <cuda_runtime.h>
#include <cstdint>

// Problem constants
#define BATCH   2
#define NVIEW   6
#define XD      8
#define YD      8
#define W1D     8
#define W2D     8
#define DIM     128
#define HEADS   4
#define DHEAD   32
#define HDIM    128
#define LWIN    64
#define QTOK    384
#define NBL     128
#define TOKENS  49152
#define R2ROWS  8192
#define EPS     1e-5f
#define FULLMASK 0xffffffffu
#define QSCALE  (0.1767766952966369f * 1.4426950408889634f)

// Scratch: bf16 intermediates packed as uint32 (2 bf16/word, 64 words/row)
__device__ uint32_t g_qp[TOKENS * 64];
__device__ uint32_t g_kp[TOKENS * 64];
__device__ uint32_t g_vp[TOKENS * 64];
__device__ uint32_t g_at[TOKENS * 64];
// Pre-packed transposed weights, 4 slots: wq*gq, wk*gk, wv*gv, wp
__device__ uint32_t g_wt[4 * 128 * 64];
// Aux per qkv mat: [mat][0..127]=gW (col sums of g*W), [mat][128..255]=b@W+bias
__device__ float g_aux[3 * 256];

__device__ __forceinline__ uint32_t packbf(float lo, float hi) {
    uint32_t d;
    asm("cvt.rn.bf16x2.f32 %0, %1, %2;" : "=r"(d) : "f"(hi), "f"(lo));
    return d;
}
__device__ __forceinline__ float bflo(uint32_t u) { return __uint_as_float(u << 16); }
__device__ __forceinline__ float bfhi(uint32_t u) { return __uint_as_float(u & 0xffff0000u); }

__device__ __forceinline__ void mma16(float* d, const uint32_t* a, const uint32_t* b) {
    asm volatile("mma.sync.aligned.m16n8k16.row.col.f32.bf16.bf16.f32 "
        "{%0,%1,%2,%3}, {%4,%5,%6,%7}, {%8,%9}, {%0,%1,%2,%3};"
        : "+f"(d[0]), "+f"(d[1]), "+f"(d[2]), "+f"(d[3])
        : "r"(a[0]), "r"(a[1]), "r"(a[2]), "r"(a[3]), "r"(b[0]), "r"(b[1]));
}
__device__ __forceinline__ void ldsm4(uint32_t* r, uint32_t saddr) {
    asm volatile("ldmatrix.sync.aligned.m8n8.x4.shared.b16 {%0,%1,%2,%3}, [%4];"
        : "=r"(r[0]), "=r"(r[1]), "=r"(r[2]), "=r"(r[3]) : "r"(saddr));
}

// ---------------------------------------------------------------------------
// Kernel 0: pre-pack weights (gamma-folded for q/k/v; qmul folded into q) and
// compute aux vectors gW = colsum(g*W), bWb = b@W + bias.
// ---------------------------------------------------------------------------
__global__ __launch_bounds__(128) void pack_w_kernel(
    const float* __restrict__ wq, const float* __restrict__ wk,
    const float* __restrict__ wv, const float* __restrict__ wp,
    const float* __restrict__ lnq_g, const float* __restrict__ lnq_b,
    const float* __restrict__ lnk_g, const float* __restrict__ lnk_b,
    const float* __restrict__ lnv_g, const float* __restrict__ lnv_b,
    const float* __restrict__ bq, const float* __restrict__ bk,
    const float* __restrict__ bv)
{
    int bx = blockIdx.x;
    if (bx < 64) {
        int mat   = bx >> 4;
        int chunk = bx & 15;
        const float* W = (mat == 0) ? wq : (mat == 1) ? wk : (mat == 2) ? wv : wp;
        const float* g = (mat == 0) ? lnq_g : (mat == 1) ? lnk_g : lnv_g;
        float scale = (mat == 0) ? QSCALE : 1.0f;
        uint32_t* dst = g_wt + mat * 8192;
        #pragma unroll
        for (int it = 0; it < 4; ++it) {
            int i = chunk * 512 + it * 128 + threadIdx.x;
            int k2 = i >> 7, n = i & 127;
            float w0 = W[(2 * k2) * 128 + n];
            float w1 = W[(2 * k2 + 1) * 128 + n];
            if (mat < 3)
                dst[n * 64 + k2] = packbf(g[2 * k2] * w0 * scale,
                                          g[2 * k2 + 1] * w1 * scale);
            else
                dst[n * 64 + k2] = packbf(w0, w1);
        }
    } else {
        int mat = bx - 64;   // 0..2
        const float* W    = (mat == 0) ? wq : (mat == 1) ? wk : wv;
        const float* g    = (mat == 0) ? lnq_g : (mat == 1) ? lnk_g : lnv_g;
        const float* b    = (mat == 0) ? lnq_b : (mat == 1) ? lnk_b : lnv_b;
        const float* bias = (mat == 0) ? bq : (mat == 1) ? bk : bv;
        float scale = (mat == 0) ? QSCALE : 1.0f;
        int n = threadIdx.x;
        float gw = 0.f, bw = 0.f;
        #pragma unroll 8
        for (int k = 0; k < 128; ++k) {
            float w = W[k * 128 + n];
            gw += g[k] * w;
            bw += b[k] * w;
        }
        g_aux[mat * 256 + n]       = gw * scale;
        g_aux[mat * 256 + 128 + n] = (bw + bias[n]) * scale;
    }
}

// ---------------------------------------------------------------------------
// Kernel 1: fold + projection GEMM, LN folded into the epilogue:
//   out = rs*(x @ W') + (-rs*mu)*gW + bWb
// Phase A STREAMS the convert-copy (small live set -> no spills).
// ---------------------------------------------------------------------------
#define XS_WSTR 68
#define XS_BSTR 272
#define WT_WOFF (64 * XS_WSTR)
#define WT_BOFF (64 * XS_BSTR)
#define STATS_WOFF ((64 + 128) * XS_WSTR)
#define K1_SMEM ((STATS_WOFF + 128) * 4)

__global__ __launch_bounds__(256, 3) void ln_proj_mma(
    const float* __restrict__ q, const float* __restrict__ k,
    const float* __restrict__ v)
{
    extern __shared__ uint32_t smw[];
    float* sf = (float*)smw;
    uint32_t sbase = (uint32_t)__cvta_generic_to_shared(smw);

    const float* src; uint32_t* dst;
    int mat = blockIdx.y;
    if (mat == 0)      { src = q; dst = g_qp; }
    else if (mat == 1) { src = k; dst = g_kp; }
    else               { src = v; dst = g_vp; }

    int tid  = threadIdx.x;
    int warp = tid >> 5;
    int lane = tid & 31;
    int row0 = blockIdx.x * 64;

    // Wt fill from pre-packed gmem
    {
        const uint4* wsrc = (const uint4*)(g_wt + mat * 8192);
        #pragma unroll
        for (int it = 0; it < 8; ++it) {
            int j  = it * 256 + tid;
            int n  = j >> 4, c4 = j & 15;
            *(uint4*)(smw + WT_WOFF + n * XS_WSTR + c4 * 4) = wsrc[j];
        }
    }

    // Hoisted fold decode: tile = fixed (b,l,n), contiguous 64x128 source block
    int bIdx = row0 / (LWIN * QTOK);
    int rem  = row0 % (LWIN * QTOK);
    int l = rem / QTOK;
    int t = rem % QTOK;
    int nv = t >> 6;
    int x = l >> 3, y = l & 7;
    const float* srcBase = src +
        (size_t)((((bIdx * NVIEW + nv) * XD + x) * YD + y)) * (W1D * W2D * DIM);

    // Phase A: 4 threads per token, STREAMED convert-copy + stats.
    {
        int tok = tid >> 2;      // 0..63
        int qd  = tid & 3;       // quarter of the row
        const float4* xp = (const float4*)(srcBase + tok * DIM + qd * 32);
        uint32_t* xrow = smw + tok * XS_WSTR + qd * 16;
        float s = 0.f, ss = 0.f;
        #pragma unroll 4
        for (int j = 0; j < 8; ++j) {
            float4 xv = xp[j];
            s  += xv.x + xv.y + xv.z + xv.w;
            ss += xv.x * xv.x + xv.y * xv.y + xv.z * xv.z + xv.w * xv.w;
            xrow[j * 2    ] = packbf(xv.x, xv.y);
            xrow[j * 2 + 1] = packbf(xv.z, xv.w);
        }
        s  += __shfl_xor_sync(FULLMASK, s,  1);
        s  += __shfl_xor_sync(FULLMASK, s,  2);
        ss += __shfl_xor_sync(FULLMASK, ss, 1);
        ss += __shfl_xor_sync(FULLMASK, ss, 2);
        if (qd == 0) {
            float mu  = s * (1.0f / 128.0f);
            float var = ss * (1.0f / 128.0f) - mu * mu;
            float rs  = rsqrtf(var + EPS);
            sf[STATS_WOFF + tok]      = rs;
            sf[STATS_WOFF + 64 + tok] = -rs * mu;
        }
    }
    __syncthreads();

    int mg = warp >> 2, ng = warp & 3;
    int g  = lane >> 2, c = lane & 3;

    float acc[2][4][4];
    #pragma unroll
    for (int mt = 0; mt < 2; ++mt)
        #pragma unroll
        for (int nt = 0; nt < 4; ++nt)
            { acc[mt][nt][0]=0.f; acc[mt][nt][1]=0.f; acc[mt][nt][2]=0.f; acc[mt][nt][3]=0.f; }

    int khi = (lane & 16) >> 1;
    uint32_t aA0 = sbase + (mg * 32 + (lane & 15)) * XS_BSTR + khi * 2;
    uint32_t aA1 = aA0 + 16 * XS_BSTR;
    uint32_t aB0 = sbase + WT_BOFF
                 + (ng * 32 + (lane & 7) + khi) * XS_BSTR + (lane & 8) * 2;
    uint32_t aB1 = aB0 + 16 * XS_BSTR;

    #pragma unroll
    for (int kst = 0; kst < 8; ++kst) {
        uint32_t a0[4], a1[4], b0[4], b1[4];
        ldsm4(a0, aA0 + kst * 32);
        ldsm4(a1, aA1 + kst * 32);
        ldsm4(b0, aB0 + kst * 32);
        ldsm4(b1, aB1 + kst * 32);
        mma16(acc[0][0], a0, b0);     mma16(acc[0][1], a0, b0 + 2);
        mma16(acc[0][2], a0, b1);     mma16(acc[0][3], a0, b1 + 2);
        mma16(acc[1][0], a1, b0);     mma16(acc[1][1], a1, b0 + 2);
        mma16(acc[1][2], a1, b1);     mma16(acc[1][3], a1, b1 + 2);
    }

    // Epilogue: out = rs*acc + nmu*gW + bWb
    float rs0 = sf[STATS_WOFF +      mg * 32 + g];
    float nm0 = sf[STATS_WOFF + 64 + mg * 32 + g];
    float rs1 = sf[STATS_WOFF +      mg * 32 + g + 8];
    float nm1 = sf[STATS_WOFF + 64 + mg * 32 + g + 8];
    float rs2 = sf[STATS_WOFF +      mg * 32 + 16 + g];
    float nm2 = sf[STATS_WOFF + 64 + mg * 32 + 16 + g];
    float rs3 = sf[STATS_WOFF +      mg * 32 + 16 + g + 8];
    float nm3 = sf[STATS_WOFF + 64 + mg * 32 + 16 + g + 8];

    #pragma unroll
    for (int nt = 0; nt < 4; ++nt) {
        int col = ng * 32 + nt * 8 + c * 2;
        float2 gw2 = *(const float2*)(g_aux + mat * 256 + col);
        float2 bb2 = *(const float2*)(g_aux + mat * 256 + 128 + col);
        int wcol = ng * 16 + nt * 4 + c;
        #pragma unroll
        for (int mt = 0; mt < 2; ++mt) {
            float rsA = (mt == 0) ? rs0 : rs2;
            float nmA = (mt == 0) ? nm0 : nm2;
            float rsB = (mt == 0) ? rs1 : rs3;
            float nmB = (mt == 0) ? nm1 : nm3;
            int rr = row0 + mg * 32 + mt * 16 + g;
            float oA0 = acc[mt][nt][0] * rsA + (nmA * gw2.x + bb2.x);
            float oA1 = acc[mt][nt][1] * rsA + (nmA * gw2.y + bb2.y);
            float oB0 = acc[mt][nt][2] * rsB + (nmB * gw2.x + bb2.x);
            float oB1 = acc[mt][nt][3] * rsB + (nmB * gw2.y + bb2.y);
            dst[(size_t)rr * 64 + wcol]       = packbf(oA0, oA1);
            dst[(size_t)(rr + 8) * 64 + wcol] = packbf(oB0, oB1);
        }
    }
}

// ---------------------------------------------------------------------------
// Kernel 2: flash attention (unchanged). One CTA per (b,l,head).
// ---------------------------------------------------------------------------
#define KS_WSTR 20
#define KS_BSTR 80
#define VT_WOFF (QTOK * KS_WSTR)
#define VT_BOFF (QTOK * KS_BSTR)
#define VT_WSTR 196
#define VT_BSTR 784
#define K2_SMEM (VT_BOFF + 32 * VT_BSTR)

__global__ __launch_bounds__(768, 1) void attn_mma()
{
    extern __shared__ uint32_t smw[];
    uint32_t sbase = (uint32_t)__cvta_generic_to_shared(smw);

    int bx = blockIdx.x;
    int bl = bx >> 2;
    int m  = bx & 3;
    size_t base_w = (size_t)bl * QTOK * 64 + m * 16;

    int tid = threadIdx.x, warp = tid >> 5, lane = tid & 31;
    int g = lane >> 2, c = lane & 3;

    #pragma unroll
    for (int it = 0; it < 2; ++it) {
        int i = it * 768 + tid;
        int row = i >> 2, c4 = i & 3;
        uint4 u = ((const uint4*)(g_kp + base_w + (size_t)row * 64))[c4];
        *(uint4*)(smw + row * KS_WSTR + c4 * 4) = u;
    }
    {
        int i = tid;
        int r2 = i >> 2, c4 = i & 3;
        uint4 u0 = ((const uint4*)(g_vp + base_w + (size_t)(2 * r2)     * 64))[c4];
        uint4 u1 = ((const uint4*)(g_vp + base_w + (size_t)(2 * r2 + 1) * 64))[c4];
        int w0 = c4 * 4;
        smw[VT_WOFF + (2*w0    ) * VT_WSTR + r2] = __byte_perm(u0.x, u1.x, 0x5410);
        smw[VT_WOFF + (2*w0 + 1) * VT_WSTR + r2] = __byte_perm(u0.x, u1.x, 0x7632);
        smw[VT_WOFF + (2*w0 + 2) * VT_WSTR + r2] = __byte_perm(u0.y, u1.y, 0x5410);
        smw[VT_WOFF + (2*w0 + 3) * VT_WSTR + r2] = __byte_perm(u0.y, u1.y, 0x7632);
        smw[VT_WOFF + (2*w0 + 4) * VT_WSTR + r2] = __byte_perm(u0.z, u1.z, 0x5410);
        smw[VT_WOFF + (2*w0 + 5) * VT_WSTR + r2] = __byte_perm(u0.z, u1.z, 0x7632);
        smw[VT_WOFF + (2*w0 + 6) * VT_WSTR + r2] = __byte_perm(u0.w, u1.w, 0x5410);
        smw[VT_WOFF + (2*w0 + 7) * VT_WSTR + r2] = __byte_perm(u0.w, u1.w, 0x7632);
    }

    int q0 = warp * 16;
    uint32_t qa[2][4];
    {
        const uint32_t* qr0 = g_qp + base_w + (size_t)(q0 + g) * 64;
        const uint32_t* qr1 = g_qp + base_w + (size_t)(q0 + g + 8) * 64;
        #pragma unroll
        for (int kst = 0; kst < 2; ++kst) {
            qa[kst][0] = qr0[kst * 8 + c    ];
            qa[kst][1] = qr1[kst * 8 + c    ];
            qa[kst][2] = qr0[kst * 8 + c + 4];
            qa[kst][3] = qr1[kst * 8 + c + 4];
        }
    }
    __syncthreads();

    float o[4][4];
    #pragma unroll
    for (int nt = 0; nt < 4; ++nt)
        { o[nt][0]=0.f; o[nt][1]=0.f; o[nt][2]=0.f; o[nt][3]=0.f; }
    float lp0 = 0.f, lp1 = 0.f;

    int rhi = (lane & 16) >> 1;
    uint32_t aK = sbase + ((lane & 7) + rhi) * KS_BSTR + (lane & 8) * 2;
    uint32_t aV = sbase + VT_BOFF + ((lane & 7) + rhi) * VT_BSTR + (lane & 8) * 2;

    for (int kc = 0; kc < QTOK; kc += 32) {
        float s[4][4];
        #pragma unroll
        for (int nt = 0; nt < 4; ++nt)
            { s[nt][0]=0.f; s[nt][1]=0.f; s[nt][2]=0.f; s[nt][3]=0.f; }

        #pragma unroll
        for (int kst = 0; kst < 2; ++kst) {
            uint32_t b0[4], b1[4];
            ldsm4(b0, aK + (kc)      * KS_BSTR + kst * 32);
            ldsm4(b1, aK + (kc + 16) * KS_BSTR + kst * 32);
            mma16(s[0], qa[kst], b0);     mma16(s[1], qa[kst], b0 + 2);
            mma16(s[2], qa[kst], b1);     mma16(s[3], qa[kst], b1 + 2);
        }

        #pragma unroll
        for (int nt = 0; nt < 4; ++nt) {
            s[nt][0] = exp2f(s[nt][0]);
            s[nt][1] = exp2f(s[nt][1]);
            s[nt][2] = exp2f(s[nt][2]);
            s[nt][3] = exp2f(s[nt][3]);
            lp0 += s[nt][0] + s[nt][1];
            lp1 += s[nt][2] + s[nt][3];
        }

        #pragma unroll
        for (int kt = 0; kt < 2; ++kt) {
            uint32_t pa[4];
            pa[0] = packbf(s[2*kt  ][0], s[2*kt  ][1]);
            pa[1] = packbf(s[2*kt  ][2], s[2*kt  ][3]);
            pa[2] = packbf(s[2*kt+1][0], s[2*kt+1][1]);
            pa[3] = packbf(s[2*kt+1][2], s[2*kt+1][3]);
            int kbase = kc + kt * 16;
            uint32_t v0[4], v1[4];
            ldsm4(v0, aV                + kbase * 2);
            ldsm4(v1, aV + 16 * VT_BSTR + kbase * 2);
            mma16(o[0], pa, v0);     mma16(o[1], pa, v0 + 2);
            mma16(o[2], pa, v1);     mma16(o[3], pa, v1 + 2);
        }
    }

    lp0 += __shfl_xor_sync(FULLMASK, lp0, 1);
    lp0 += __shfl_xor_sync(FULLMASK, lp0, 2);
    lp1 += __shfl_xor_sync(FULLMASK, lp1, 1);
    lp1 += __shfl_xor_sync(FULLMASK, lp1, 2);

    float inv0 = 1.0f / lp0;
    float inv1 = 1.0f / lp1;
    int r0 = q0 + g;
    #pragma unroll
    for (int nt = 0; nt < 4; ++nt) {
        int wcol = nt * 4 + c;
        g_at[base_w + (size_t)r0 * 64 + wcol]       = packbf(o[nt][0] * inv0, o[nt][1] * inv0);
        g_at[base_w + (size_t)(r0 + 8) * 64 + wcol] = packbf(o[nt][2] * inv1, o[nt][3] * inv1);
    }
}

// ---------------------------------------------------------------------------
// Kernel 3: mean-over-views + output projection (bf16 mma) + bias + skip.
// 32-row tiles, grid=256, block=128.
// ---------------------------------------------------------------------------
#define WT3_WOFF (32 * XS_WSTR)
#define WT3_BOFF (32 * XS_BSTR)
#define K3_SMEM ((32 + 128) * XS_BSTR)

__global__ __launch_bounds__(128) void out_proj_mma(
    const float* __restrict__ bp,
    const float* __restrict__ skip, float* __restrict__ out)
{
    extern __shared__ uint32_t smw[];
    uint32_t sbase = (uint32_t)__cvta_generic_to_shared(smw);

    int tid  = threadIdx.x;
    int warp = tid >> 5;
    int lane = tid & 31;
    int row0 = blockIdx.x * 32;

    {
        const uint4* wsrc = (const uint4*)(g_wt + 3 * 8192);
        #pragma unroll
        for (int it = 0; it < 16; ++it) {
            int j  = it * 128 + tid;
            int n  = j >> 4, c4 = j & 15;
            *(uint4*)(smw + WT3_WOFF + n * XS_WSTR + c4 * 4) = wsrc[j];
        }
    }

    // Xs = mean over n, uint4 loads
    #pragma unroll
    for (int it = 0; it < 4; ++it) {
        int i = it * 128 + tid;
        int rloc = i >> 4, c4 = i & 15;
        int r2 = row0 + rloc;
        int bl = r2 >> 6;
        int wr = r2 & 63;
        const uint4* srcp = (const uint4*)(g_at + (size_t)(bl * QTOK + wr) * 64) + c4;
        float a0=0.f,a1=0.f,a2=0.f,a3=0.f,a4=0.f,a5=0.f,a6=0.f,a7=0.f;
        #pragma unroll
        for (int n = 0; n < NVIEW; ++n) {
            uint4 u = srcp[n * 64 * 16];
            a0 += bflo(u.x); a1 += bfhi(u.x);
            a2 += bflo(u.y); a3 += bfhi(u.y);
            a4 += bflo(u.z); a5 += bfhi(u.z);
            a6 += bflo(u.w); a7 += bfhi(u.w);
        }
        const float iv = 1.0f / 6.0f;
        uint4 ov;
        ov.x = packbf(a0 * iv, a1 * iv);
        ov.y = packbf(a2 * iv, a3 * iv);
        ov.z = packbf(a4 * iv, a5 * iv);
        ov.w = packbf(a6 * iv, a7 * iv);
        *(uint4*)(smw + rloc * XS_WSTR + c4 * 4) = ov;
    }
    __syncthreads();

    int ng = warp;
    int g  = lane >> 2, c = lane & 3;

    float acc[2][4][4];
    #pragma unroll
    for (int mt = 0; mt < 2; ++mt)
        #pragma unroll
        for (int nt = 0; nt < 4; ++nt)
            { acc[mt][nt][0]=0.f; acc[mt][nt][1]=0.f; acc[mt][nt][2]=0.f; acc[mt][nt][3]=0.f; }

    int khi = (lane & 16) >> 1;
    uint32_t aA0 = sbase + (lane & 15) * XS_BSTR + khi * 2;
    uint32_t aA1 = aA0 + 16 * XS_BSTR;
    uint32_t aB0 = sbase + WT3_BOFF
                 + (ng * 32 + (lane & 7) + khi) * XS_BSTR + (lane & 8) * 2;
    uint32_t aB1 = aB0 + 16 * XS_BSTR;

    #pragma unroll
    for (int kst = 0; kst < 8; ++kst) {
        uint32_t a0[4], a1[4], b0[4], b1[4];
        ldsm4(a0, aA0 + kst * 32);
        ldsm4(a1, aA1 + kst * 32);
        ldsm4(b0, aB0 + kst * 32);
        ldsm4(b1, aB1 + kst * 32);
        mma16(acc[0][0], a0, b0);     mma16(acc[0][1], a0, b0 + 2);
        mma16(acc[0][2], a0, b1);     mma16(acc[0][3], a0, b1 + 2);
        mma16(acc[1][0], a1, b0);     mma16(acc[1][1], a1, b0 + 2);
        mma16(acc[1][2], a1, b1);     mma16(acc[1][3], a1, b1 + 2);
    }

    #pragma unroll
    for (int nt = 0; nt < 4; ++nt) {
        int col = ng * 32 + nt * 8 + c * 2;
        float2 bv2 = *(const float2*)(bp + col);
        #pragma unroll
        for (int mt = 0; mt < 2; ++mt) {
            int rr = row0 + mt * 16 + g;
            float2 sk0 = *(const float2*)(skip + (size_t)rr * 128 + col);
            float2 sk1 = *(const float2*)(skip + (size_t)(rr + 8) * 128 + col);
            float2 o0 = { acc[mt][nt][0] + bv2.x + sk0.x, acc[mt][nt][1] + bv2.y + sk0.y };
            float2 o1 = { acc[mt][nt][2] + bv2.x + sk1.x, acc[mt][nt][3] + bv2.y + sk1.y };
            *(float2*)(out + (size_t)rr * 128 + col)       = o0;
            *(float2*)(out + (size_t)(rr + 8) * 128 + col) = o1;
        }
    }
}

// ---------------------------------------------------------------------------
extern "C" void kernel_launch(void* const* d_in, const int* in_sizes, int n_in,
                              void* d_out, int out_size)
{
    const float* q     = (const float*)d_in[0];
    const float* k     = (const float*)d_in[1];
    const float* v     = (const float*)d_in[2];
    const float* skip  = (const float*)d_in[3];
    const float* lnq_g = (const float*)d_in[4];
    const float* lnq_b = (const float*)d_in[5];
    const float* lnk_g = (const float*)d_in[6];
    const float* lnk_b = (const float*)d_in[7];
    const float* lnv_g = (const float*)d_in[8];
    const float* lnv_b = (const float*)d_in[9];
    const float* wq    = (const float*)d_in[10];
    const float* bq    = (const float*)d_in[11];
    const float* wk    = (const float*)d_in[12];
    const float* bk    = (const float*)d_in[13];
    const float* wv    = (const float*)d_in[14];
    const float* bv    = (const float*)d_in[15];
    const float* wp    = (const float*)d_in[16];
    const float* bp    = (const float*)d_in[17];
    float* out = (float*)d_out;

    cudaFuncSetAttribute(ln_proj_mma,  cudaFuncAttributeMaxDynamicSharedMemorySize, K1_SMEM);
    cudaFuncSetAttribute(attn_mma,     cudaFuncAttributeMaxDynamicSharedMemorySize, K2_SMEM);
    cudaFuncSetAttribute(out_proj_mma, cudaFuncAttributeMaxDynamicSharedMemorySize, K3_SMEM);

    pack_w_kernel<<<67, 128>>>(wq, wk, wv, wp,
                               lnq_g, lnq_b, lnk_g, lnk_b, lnv_g, lnv_b,
                               bq, bk, bv);

    ln_proj_mma<<<dim3(TOKENS / 64, 3), 256, K1_SMEM>>>(q, k, v);

    attn_mma<<<NBL * HEADS, 768, K2_SMEM>>>();

    out_proj_mma<<<R2ROWS / 32, 128, K3_SMEM>>>(bp, skip, out);
}

// round 13
// speedup vs baseline: 1.6325x; 1.6325x over previous
#include <cuda_runtime.h>
#include <cstdint>

// Problem constants
#define BATCH   2
#define NVIEW   6
#define XD      8
#define YD      8
#define W1D     8
#define W2D     8
#define DIM     128
#define HEADS   4
#define DHEAD   32
#define HDIM    128
#define LWIN    64
#define QTOK    384
#define NBL     128
#define TOKENS  49152
#define R2ROWS  8192
#define EPS     1e-5f
#define FULLMASK 0xffffffffu
#define QSCALE  (0.1767766952966369f * 1.4426950408889634f)

// Scratch: bf16 intermediates packed as uint32 (2 bf16/word, 64 words/row)
__device__ uint32_t g_qp[TOKENS * 64];
__device__ uint32_t g_kp[TOKENS * 64];
__device__ uint32_t g_vp[TOKENS * 64];
__device__ uint32_t g_at[TOKENS * 64];
// Pre-packed transposed weights, 4 slots: wq*gq*qs, wk*gk, wv*gv, wp
__device__ uint32_t g_wt[4 * 128 * 64];
// Aux per qkv mat: [mat][0..127]=gW colsums, [mat][128..255]=b@W+bias
__device__ float g_aux[3 * 256];

__device__ __forceinline__ uint32_t packbf(float lo, float hi) {
    uint32_t d;
    asm("cvt.rn.bf16x2.f32 %0, %1, %2;" : "=r"(d) : "f"(hi), "f"(lo));
    return d;
}
__device__ __forceinline__ float bflo(uint32_t u) { return __uint_as_float(u << 16); }
__device__ __forceinline__ float bfhi(uint32_t u) { return __uint_as_float(u & 0xffff0000u); }

__device__ __forceinline__ void mma16(float* d, const uint32_t* a, const uint32_t* b) {
    asm volatile("mma.sync.aligned.m16n8k16.row.col.f32.bf16.bf16.f32 "
        "{%0,%1,%2,%3}, {%4,%5,%6,%7}, {%8,%9}, {%0,%1,%2,%3};"
        : "+f"(d[0]), "+f"(d[1]), "+f"(d[2]), "+f"(d[3])
        : "r"(a[0]), "r"(a[1]), "r"(a[2]), "r"(a[3]), "r"(b[0]), "r"(b[1]));
}
__device__ __forceinline__ void ldsm4(uint32_t* r, uint32_t saddr) {
    asm volatile("ldmatrix.sync.aligned.m8n8.x4.shared.b16 {%0,%1,%2,%3}, [%4];"
        : "=r"(r[0]), "=r"(r[1]), "=r"(r[2]), "=r"(r[3]) : "r"(saddr));
}

// ---------------------------------------------------------------------------
// Kernel 0: pre-pack weights (gamma folded for q/k/v; qscale folded into q)
// and aux vectors gW = colsum(g*W), bWb = b@W + bias.
// ---------------------------------------------------------------------------
__global__ __launch_bounds__(128) void pack_w_kernel(
    const float* __restrict__ wq, const float* __restrict__ wk,
    const float* __restrict__ wv, const float* __restrict__ wp,
    const float* __restrict__ lnq_g, const float* __restrict__ lnq_b,
    const float* __restrict__ lnk_g, const float* __restrict__ lnk_b,
    const float* __restrict__ lnv_g, const float* __restrict__ lnv_b,
    const float* __restrict__ bq, const float* __restrict__ bk,
    const float* __restrict__ bv)
{
    int bx = blockIdx.x;
    if (bx < 64) {
        int mat   = bx >> 4;
        int chunk = bx & 15;
        const float* W = (mat == 0) ? wq : (mat == 1) ? wk : (mat == 2) ? wv : wp;
        const float* g = (mat == 0) ? lnq_g : (mat == 1) ? lnk_g : lnv_g;
        float scale = (mat == 0) ? QSCALE : 1.0f;
        uint32_t* dst = g_wt + mat * 8192;
        #pragma unroll
        for (int it = 0; it < 4; ++it) {
            int i = chunk * 512 + it * 128 + threadIdx.x;
            int k2 = i >> 7, n = i & 127;
            float w0 = W[(2 * k2) * 128 + n];
            float w1 = W[(2 * k2 + 1) * 128 + n];
            if (mat < 3)
                dst[n * 64 + k2] = packbf(g[2 * k2] * w0 * scale,
                                          g[2 * k2 + 1] * w1 * scale);
            else
                dst[n * 64 + k2] = packbf(w0, w1);
        }
    } else {
        int mat = bx - 64;   // 0..2
        const float* W    = (mat == 0) ? wq : (mat == 1) ? wk : wv;
        const float* g    = (mat == 0) ? lnq_g : (mat == 1) ? lnk_g : lnv_g;
        const float* b    = (mat == 0) ? lnq_b : (mat == 1) ? lnk_b : lnv_b;
        const float* bias = (mat == 0) ? bq : (mat == 1) ? bk : bv;
        float scale = (mat == 0) ? QSCALE : 1.0f;
        int n = threadIdx.x;
        float gw = 0.f, bw = 0.f;
        #pragma unroll 8
        for (int k = 0; k < 128; ++k) {
            float w = W[k * 128 + n];
            gw += g[k] * w;
            bw += b[k] * w;
        }
        g_aux[mat * 256 + n]       = gw * scale;
        g_aux[mat * 256 + 128 + n] = (bw + bias[n]) * scale;
    }
}

// ---------------------------------------------------------------------------
// Kernel 1: fold + projection GEMM, LN folded into the epilogue:
//   out = rs*(x @ W') + (-rs*mu)*gW + bWb
// Phase A uses R10's PROVEN pattern: warp per token, coalesced float4 loads,
// shfl butterfly; stores RAW x (no normalize) + per-token stats.
// ---------------------------------------------------------------------------
#define XS_WSTR 68
#define XS_BSTR 272
#define WT_WOFF (64 * XS_WSTR)
#define WT_BOFF (64 * XS_BSTR)
#define STATS_WOFF ((64 + 128) * XS_WSTR)
#define K1_SMEM ((STATS_WOFF + 128) * 4)

__global__ __launch_bounds__(256, 3) void ln_proj_mma(
    const float* __restrict__ q, const float* __restrict__ k,
    const float* __restrict__ v)
{
    extern __shared__ uint32_t smw[];
    float* sf = (float*)smw;
    uint32_t sbase = (uint32_t)__cvta_generic_to_shared(smw);

    const float* src; uint32_t* dst;
    int mat = blockIdx.y;
    if (mat == 0)      { src = q; dst = g_qp; }
    else if (mat == 1) { src = k; dst = g_kp; }
    else               { src = v; dst = g_vp; }

    int tid  = threadIdx.x;
    int warp = tid >> 5;
    int lane = tid & 31;
    int row0 = blockIdx.x * 64;

    // Wt fill from pre-packed gmem
    {
        const uint4* wsrc = (const uint4*)(g_wt + mat * 8192);
        #pragma unroll
        for (int it = 0; it < 8; ++it) {
            int j  = it * 256 + tid;
            int n  = j >> 4, c4 = j & 15;
            *(uint4*)(smw + WT_WOFF + n * XS_WSTR + c4 * 4) = wsrc[j];
        }
    }

    // Hoisted fold decode: tile = fixed (b,l,n), contiguous 64x128 source block
    int bIdx = row0 / (LWIN * QTOK);
    int rem  = row0 % (LWIN * QTOK);
    int l = rem / QTOK;
    int t = rem % QTOK;
    int nv = t >> 6;
    int x = l >> 3, y = l & 7;
    const float* srcBase = src +
        (size_t)((((bIdx * NVIEW + nv) * XD + x) * YD + y)) * (W1D * W2D * DIM);

    // Phase A: warp per token (R10 pattern), raw bf16 store + stats
    #pragma unroll
    for (int it = 0; it < 8; ++it) {
        int rloc = it * 8 + warp;
        float4 xv = ((const float4*)(srcBase + rloc * DIM))[lane];
        float s  = xv.x + xv.y + xv.z + xv.w;
        float ss = xv.x * xv.x + xv.y * xv.y + xv.z * xv.z + xv.w * xv.w;
        #pragma unroll
        for (int o = 16; o; o >>= 1) {
            s  += __shfl_xor_sync(FULLMASK, s,  o);
            ss += __shfl_xor_sync(FULLMASK, ss, o);
        }
        smw[rloc * XS_WSTR + lane * 2    ] = packbf(xv.x, xv.y);
        smw[rloc * XS_WSTR + lane * 2 + 1] = packbf(xv.z, xv.w);
        if (lane == 0) {
            float mu  = s * (1.0f / 128.0f);
            float var = ss * (1.0f / 128.0f) - mu * mu;
            float rs  = rsqrtf(var + EPS);
            sf[STATS_WOFF + rloc]      = rs;
            sf[STATS_WOFF + 64 + rloc] = -rs * mu;
        }
    }
    __syncthreads();

    int mg = warp >> 2, ng = warp & 3;
    int g  = lane >> 2, c = lane & 3;

    float acc[2][4][4];
    #pragma unroll
    for (int mt = 0; mt < 2; ++mt)
        #pragma unroll
        for (int nt = 0; nt < 4; ++nt)
            { acc[mt][nt][0]=0.f; acc[mt][nt][1]=0.f; acc[mt][nt][2]=0.f; acc[mt][nt][3]=0.f; }

    int khi = (lane & 16) >> 1;
    uint32_t aA0 = sbase + (mg * 32 + (lane & 15)) * XS_BSTR + khi * 2;
    uint32_t aA1 = aA0 + 16 * XS_BSTR;
    uint32_t aB0 = sbase + WT_BOFF
                 + (ng * 32 + (lane & 7) + khi) * XS_BSTR + (lane & 8) * 2;
    uint32_t aB1 = aB0 + 16 * XS_BSTR;

    #pragma unroll
    for (int kst = 0; kst < 8; ++kst) {
        uint32_t a0[4], a1[4], b0[4], b1[4];
        ldsm4(a0, aA0 + kst * 32);
        ldsm4(a1, aA1 + kst * 32);
        ldsm4(b0, aB0 + kst * 32);
        ldsm4(b1, aB1 + kst * 32);
        mma16(acc[0][0], a0, b0);     mma16(acc[0][1], a0, b0 + 2);
        mma16(acc[0][2], a0, b1);     mma16(acc[0][3], a0, b1 + 2);
        mma16(acc[1][0], a1, b0);     mma16(acc[1][1], a1, b0 + 2);
        mma16(acc[1][2], a1, b1);     mma16(acc[1][3], a1, b1 + 2);
    }

    // Epilogue: out = rs*acc + nmu*gW + bWb (validated in R11/R12)
    float rs0 = sf[STATS_WOFF +      mg * 32 + g];
    float nm0 = sf[STATS_WOFF + 64 + mg * 32 + g];
    float rs1 = sf[STATS_WOFF +      mg * 32 + g + 8];
    float nm1 = sf[STATS_WOFF + 64 + mg * 32 + g + 8];
    float rs2 = sf[STATS_WOFF +      mg * 32 + 16 + g];
    float nm2 = sf[STATS_WOFF + 64 + mg * 32 + 16 + g];
    float rs3 = sf[STATS_WOFF +      mg * 32 + 16 + g + 8];
    float nm3 = sf[STATS_WOFF + 64 + mg * 32 + 16 + g + 8];

    #pragma unroll
    for (int nt = 0; nt < 4; ++nt) {
        int col = ng * 32 + nt * 8 + c * 2;
        float2 gw2 = *(const float2*)(g_aux + mat * 256 + col);
        float2 bb2 = *(const float2*)(g_aux + mat * 256 + 128 + col);
        int wcol = ng * 16 + nt * 4 + c;
        #pragma unroll
        for (int mt = 0; mt < 2; ++mt) {
            float rsA = (mt == 0) ? rs0 : rs2;
            float nmA = (mt == 0) ? nm0 : nm2;
            float rsB = (mt == 0) ? rs1 : rs3;
            float nmB = (mt == 0) ? nm1 : nm3;
            int rr = row0 + mg * 32 + mt * 16 + g;
            float oA0 = acc[mt][nt][0] * rsA + (nmA * gw2.x + bb2.x);
            float oA1 = acc[mt][nt][1] * rsA + (nmA * gw2.y + bb2.y);
            float oB0 = acc[mt][nt][2] * rsB + (nmB * gw2.x + bb2.x);
            float oB1 = acc[mt][nt][3] * rsB + (nmB * gw2.y + bb2.y);
            dst[(size_t)rr * 64 + wcol]       = packbf(oA0, oA1);
            dst[(size_t)(rr + 8) * 64 + wcol] = packbf(oB0, oB1);
        }
    }
}

// ---------------------------------------------------------------------------
// Kernel 2: flash attention (R10 exact). One CTA per (b,l,head).
// ---------------------------------------------------------------------------
#define KS_WSTR 20
#define KS_BSTR 80
#define VT_WOFF (QTOK * KS_WSTR)
#define VT_BOFF (QTOK * KS_BSTR)
#define VT_WSTR 196
#define VT_BSTR 784
#define K2_SMEM (VT_BOFF + 32 * VT_BSTR)

__global__ __launch_bounds__(768, 1) void attn_mma()
{
    extern __shared__ uint32_t smw[];
    uint32_t sbase = (uint32_t)__cvta_generic_to_shared(smw);

    int bx = blockIdx.x;
    int bl = bx >> 2;
    int m  = bx & 3;
    size_t base_w = (size_t)bl * QTOK * 64 + m * 16;

    int tid = threadIdx.x, warp = tid >> 5, lane = tid & 31;
    int g = lane >> 2, c = lane & 3;

    #pragma unroll
    for (int it = 0; it < 2; ++it) {
        int i = it * 768 + tid;
        int row = i >> 2, c4 = i & 3;
        uint4 u = ((const uint4*)(g_kp + base_w + (size_t)row * 64))[c4];
        *(uint4*)(smw + row * KS_WSTR + c4 * 4) = u;
    }
    {
        int i = tid;
        int r2 = i >> 2, c4 = i & 3;
        uint4 u0 = ((const uint4*)(g_vp + base_w + (size_t)(2 * r2)     * 64))[c4];
        uint4 u1 = ((const uint4*)(g_vp + base_w + (size_t)(2 * r2 + 1) * 64))[c4];
        int w0 = c4 * 4;
        smw[VT_WOFF + (2*w0    ) * VT_WSTR + r2] = __byte_perm(u0.x, u1.x, 0x5410);
        smw[VT_WOFF + (2*w0 + 1) * VT_WSTR + r2] = __byte_perm(u0.x, u1.x, 0x7632);
        smw[VT_WOFF + (2*w0 + 2) * VT_WSTR + r2] = __byte_perm(u0.y, u1.y, 0x5410);
        smw[VT_WOFF + (2*w0 + 3) * VT_WSTR + r2] = __byte_perm(u0.y, u1.y, 0x7632);
        smw[VT_WOFF + (2*w0 + 4) * VT_WSTR + r2] = __byte_perm(u0.z, u1.z, 0x5410);
        smw[VT_WOFF + (2*w0 + 5) * VT_WSTR + r2] = __byte_perm(u0.z, u1.z, 0x7632);
        smw[VT_WOFF + (2*w0 + 6) * VT_WSTR + r2] = __byte_perm(u0.w, u1.w, 0x5410);
        smw[VT_WOFF + (2*w0 + 7) * VT_WSTR + r2] = __byte_perm(u0.w, u1.w, 0x7632);
    }

    int q0 = warp * 16;
    uint32_t qa[2][4];
    {
        const uint32_t* qr0 = g_qp + base_w + (size_t)(q0 + g) * 64;
        const uint32_t* qr1 = g_qp + base_w + (size_t)(q0 + g + 8) * 64;
        #pragma unroll
        for (int kst = 0; kst < 2; ++kst) {
            qa[kst][0] = qr0[kst * 8 + c    ];
            qa[kst][1] = qr1[kst * 8 + c    ];
            qa[kst][2] = qr0[kst * 8 + c + 4];
            qa[kst][3] = qr1[kst * 8 + c + 4];
        }
    }
    __syncthreads();

    float o[4][4];
    #pragma unroll
    for (int nt = 0; nt < 4; ++nt)
        { o[nt][0]=0.f; o[nt][1]=0.f; o[nt][2]=0.f; o[nt][3]=0.f; }
    float lp0 = 0.f, lp1 = 0.f;

    int rhi = (lane & 16) >> 1;
    uint32_t aK = sbase + ((lane & 7) + rhi) * KS_BSTR + (lane & 8) * 2;
    uint32_t aV = sbase + VT_BOFF + ((lane & 7) + rhi) * VT_BSTR + (lane & 8) * 2;

    for (int kc = 0; kc < QTOK; kc += 32) {
        float s[4][4];
        #pragma unroll
        for (int nt = 0; nt < 4; ++nt)
            { s[nt][0]=0.f; s[nt][1]=0.f; s[nt][2]=0.f; s[nt][3]=0.f; }

        #pragma unroll
        for (int kst = 0; kst < 2; ++kst) {
            uint32_t b0[4], b1[4];
            ldsm4(b0, aK + (kc)      * KS_BSTR + kst * 32);
            ldsm4(b1, aK + (kc + 16) * KS_BSTR + kst * 32);
            mma16(s[0], qa[kst], b0);     mma16(s[1], qa[kst], b0 + 2);
            mma16(s[2], qa[kst], b1);     mma16(s[3], qa[kst], b1 + 2);
        }

        #pragma unroll
        for (int nt = 0; nt < 4; ++nt) {
            s[nt][0] = exp2f(s[nt][0]);
            s[nt][1] = exp2f(s[nt][1]);
            s[nt][2] = exp2f(s[nt][2]);
            s[nt][3] = exp2f(s[nt][3]);
            lp0 += s[nt][0] + s[nt][1];
            lp1 += s[nt][2] + s[nt][3];
        }

        #pragma unroll
        for (int kt = 0; kt < 2; ++kt) {
            uint32_t pa[4];
            pa[0] = packbf(s[2*kt  ][0], s[2*kt  ][1]);
            pa[1] = packbf(s[2*kt  ][2], s[2*kt  ][3]);
            pa[2] = packbf(s[2*kt+1][0], s[2*kt+1][1]);
            pa[3] = packbf(s[2*kt+1][2], s[2*kt+1][3]);
            int kbase = kc + kt * 16;
            uint32_t v0[4], v1[4];
            ldsm4(v0, aV                + kbase * 2);
            ldsm4(v1, aV + 16 * VT_BSTR + kbase * 2);
            mma16(o[0], pa, v0);     mma16(o[1], pa, v0 + 2);
            mma16(o[2], pa, v1);     mma16(o[3], pa, v1 + 2);
        }
    }

    lp0 += __shfl_xor_sync(FULLMASK, lp0, 1);
    lp0 += __shfl_xor_sync(FULLMASK, lp0, 2);
    lp1 += __shfl_xor_sync(FULLMASK, lp1, 1);
    lp1 += __shfl_xor_sync(FULLMASK, lp1, 2);

    float inv0 = 1.0f / lp0;
    float inv1 = 1.0f / lp1;
    int r0 = q0 + g;
    #pragma unroll
    for (int nt = 0; nt < 4; ++nt) {
        int wcol = nt * 4 + c;
        g_at[base_w + (size_t)r0 * 64 + wcol]       = packbf(o[nt][0] * inv0, o[nt][1] * inv0);
        g_at[base_w + (size_t)(r0 + 8) * 64 + wcol] = packbf(o[nt][2] * inv1, o[nt][3] * inv1);
    }
}

// ---------------------------------------------------------------------------
// Kernel 3: mean-over-views + output projection (bf16 mma) + bias + skip.
// R8's measured-best config: 32-row tiles, grid=256, block=128.
// ---------------------------------------------------------------------------
#define WT3_WOFF (32 * XS_WSTR)
#define WT3_BOFF (32 * XS_BSTR)
#define K3_SMEM ((32 + 128) * XS_BSTR)

__global__ __launch_bounds__(128) void out_proj_mma(
    const float* __restrict__ bp,
    const float* __restrict__ skip, float* __restrict__ out)
{
    extern __shared__ uint32_t smw[];
    uint32_t sbase = (uint32_t)__cvta_generic_to_shared(smw);

    int tid  = threadIdx.x;
    int warp = tid >> 5;
    int lane = tid & 31;
    int row0 = blockIdx.x * 32;

    {
        const uint4* wsrc = (const uint4*)(g_wt + 3 * 8192);
        #pragma unroll
        for (int it = 0; it < 16; ++it) {
            int j  = it * 128 + tid;
            int n  = j >> 4, c4 = j & 15;
            *(uint4*)(smw + WT3_WOFF + n * XS_WSTR + c4 * 4) = wsrc[j];
        }
    }

    // Xs = mean over n, uint4 loads
    #pragma unroll
    for (int it = 0; it < 4; ++it) {
        int i = it * 128 + tid;
        int rloc = i >> 4, c4 = i & 15;
        int r2 = row0 + rloc;
        int bl = r2 >> 6;
        int wr = r2 & 63;
        const uint4* srcp = (const uint4*)(g_at + (size_t)(bl * QTOK + wr) * 64) + c4;
        float a0=0.f,a1=0.f,a2=0.f,a3=0.f,a4=0.f,a5=0.f,a6=0.f,a7=0.f;
        #pragma unroll
        for (int n = 0; n < NVIEW; ++n) {
            uint4 u = srcp[n * 64 * 16];
            a0 += bflo(u.x); a1 += bfhi(u.x);
            a2 += bflo(u.y); a3 += bfhi(u.y);
            a4 += bflo(u.z); a5 += bfhi(u.z);
            a6 += bflo(u.w); a7 += bfhi(u.w);
        }
        const float iv = 1.0f / 6.0f;
        uint4 ov;
        ov.x = packbf(a0 * iv, a1 * iv);
        ov.y = packbf(a2 * iv, a3 * iv);
        ov.z = packbf(a4 * iv, a5 * iv);
        ov.w = packbf(a6 * iv, a7 * iv);
        *(uint4*)(smw + rloc * XS_WSTR + c4 * 4) = ov;
    }
    __syncthreads();

    int ng = warp;
    int g  = lane >> 2, c = lane & 3;

    float acc[2][4][4];
    #pragma unroll
    for (int mt = 0; mt < 2; ++mt)
        #pragma unroll
        for (int nt = 0; nt < 4; ++nt)
            { acc[mt][nt][0]=0.f; acc[mt][nt][1]=0.f; acc[mt][nt][2]=0.f; acc[mt][nt][3]=0.f; }

    int khi = (lane & 16) >> 1;
    uint32_t aA0 = sbase + (lane & 15) * XS_BSTR + khi * 2;
    uint32_t aA1 = aA0 + 16 * XS_BSTR;
    uint32_t aB0 = sbase + WT3_BOFF
                 + (ng * 32 + (lane & 7) + khi) * XS_BSTR + (lane & 8) * 2;
    uint32_t aB1 = aB0 + 16 * XS_BSTR;

    #pragma unroll
    for (int kst = 0; kst < 8; ++kst) {
        uint32_t a0[4], a1[4], b0[4], b1[4];
        ldsm4(a0, aA0 + kst * 32);
        ldsm4(a1, aA1 + kst * 32);
        ldsm4(b0, aB0 + kst * 32);
        ldsm4(b1, aB1 + kst * 32);
        mma16(acc[0][0], a0, b0);     mma16(acc[0][1], a0, b0 + 2);
        mma16(acc[0][2], a0, b1);     mma16(acc[0][3], a0, b1 + 2);
        mma16(acc[1][0], a1, b0);     mma16(acc[1][1], a1, b0 + 2);
        mma16(acc[1][2], a1, b1);     mma16(acc[1][3], a1, b1 + 2);
    }

    #pragma unroll
    for (int nt = 0; nt < 4; ++nt) {
        int col = ng * 32 + nt * 8 + c * 2;
        float2 bv2 = *(const float2*)(bp + col);
        #pragma unroll
        for (int mt = 0; mt < 2; ++mt) {
            int rr = row0 + mt * 16 + g;
            float2 sk0 = *(const float2*)(skip + (size_t)rr * 128 + col);
            float2 sk1 = *(const float2*)(skip + (size_t)(rr + 8) * 128 + col);
            float2 o0 = { acc[mt][nt][0] + bv2.x + sk0.x, acc[mt][nt][1] + bv2.y + sk0.y };
            float2 o1 = { acc[mt][nt][2] + bv2.x + sk1.x, acc[mt][nt][3] + bv2.y + sk1.y };
            *(float2*)(out + (size_t)rr * 128 + col)       = o0;
            *(float2*)(out + (size_t)(rr + 8) * 128 + col) = o1;
        }
    }
}

// ---------------------------------------------------------------------------
extern "C" void kernel_launch(void* const* d_in, const int* in_sizes, int n_in,
                              void* d_out, int out_size)
{
    const float* q     = (const float*)d_in[0];
    const float* k     = (const float*)d_in[1];
    const float* v     = (const float*)d_in[2];
    const float* skip  = (const float*)d_in[3];
    const float* lnq_g = (const float*)d_in[4];
    const float* lnq_b = (const float*)d_in[5];
    const float* lnk_g = (const float*)d_in[6];
    const float* lnk_b = (const float*)d_in[7];
    const float* lnv_g = (const float*)d_in[8];
    const float* lnv_b = (const float*)d_in[9];
    const float* wq    = (const float*)d_in[10];
    const float* bq    = (const float*)d_in[11];
    const float* wk    = (const float*)d_in[12];
    const float* bk    = (const float*)d_in[13];
    const float* wv    = (const float*)d_in[14];
    const float* bv    = (const float*)d_in[15];
    const float* wp    = (const float*)d_in[16];
    const float* bp    = (const float*)d_in[17];
    float* out = (float*)d_out;

    cudaFuncSetAttribute(ln_proj_mma,  cudaFuncAttributeMaxDynamicSharedMemorySize, K1_SMEM);
    cudaFuncSetAttribute(attn_mma,     cudaFuncAttributeMaxDynamicSharedMemorySize, K2_SMEM);
    cudaFuncSetAttribute(out_proj_mma, cudaFuncAttributeMaxDynamicSharedMemorySize, K3_SMEM);

    pack_w_kernel<<<67, 128>>>(wq, wk, wv, wp,
                               lnq_g, lnq_b, lnk_g, lnk_b, lnv_g, lnv_b,
                               bq, bk, bv);

    ln_proj_mma<<<dim3(TOKENS / 64, 3), 256, K1_SMEM>>>(q, k, v);

    attn_mma<<<NBL * HEADS, 768, K2_SMEM>>>();

    out_proj_mma<<<R2ROWS / 32, 128, K3_SMEM>>>(bp, skip, out);
}

// round 14
// speedup vs baseline: 1.8261x; 1.1186x over previous
#include <cuda_runtime.h>
#include <cstdint>

// Problem constants
#define BATCH   2
#define NVIEW   6
#define XD      8
#define YD      8
#define W1D     8
#define W2D     8
#define DIM     128
#define HEADS   4
#define DHEAD   32
#define HDIM    128
#define LWIN    64
#define QTOK    384
#define NBL     128
#define TOKENS  49152
#define R2ROWS  8192
#define EPS     1e-5f
#define FULLMASK 0xffffffffu
#define QSCALE  (0.1767766952966369f * 1.4426950408889634f)

// Scratch: bf16 intermediates packed as uint32 (2 bf16/word, 64 words/row)
__device__ uint32_t g_qp[TOKENS * 64];
__device__ uint32_t g_kp[TOKENS * 64];
__device__ uint32_t g_vp[TOKENS * 64];
__device__ uint32_t g_at[TOKENS * 64];
// Pre-packed transposed weights, 4 slots: wq,wk,wv,wp (no gamma folding — R10)
__device__ uint32_t g_wt[4 * 128 * 64];

__device__ __forceinline__ uint32_t packbf(float lo, float hi) {
    uint32_t d;
    asm("cvt.rn.bf16x2.f32 %0, %1, %2;" : "=r"(d) : "f"(hi), "f"(lo));
    return d;
}
__device__ __forceinline__ float bflo(uint32_t u) { return __uint_as_float(u << 16); }
__device__ __forceinline__ float bfhi(uint32_t u) { return __uint_as_float(u & 0xffff0000u); }

__device__ __forceinline__ void mma16(float* d, const uint32_t* a, const uint32_t* b) {
    asm volatile("mma.sync.aligned.m16n8k16.row.col.f32.bf16.bf16.f32 "
        "{%0,%1,%2,%3}, {%4,%5,%6,%7}, {%8,%9}, {%0,%1,%2,%3};"
        : "+f"(d[0]), "+f"(d[1]), "+f"(d[2]), "+f"(d[3])
        : "r"(a[0]), "r"(a[1]), "r"(a[2]), "r"(a[3]), "r"(b[0]), "r"(b[1]));
}
__device__ __forceinline__ void ldsm4(uint32_t* r, uint32_t saddr) {
    asm volatile("ldmatrix.sync.aligned.m8n8.x4.shared.b16 {%0,%1,%2,%3}, [%4];"
        : "=r"(r[0]), "=r"(r[1]), "=r"(r[2]), "=r"(r[3]) : "r"(saddr));
}

// ---------------------------------------------------------------------------
// Kernel 0: pre-pack weights (R10 version). grid=64, block=128.
// ---------------------------------------------------------------------------
__global__ __launch_bounds__(128) void pack_w_kernel(
    const float* __restrict__ wq, const float* __restrict__ wk,
    const float* __restrict__ wv, const float* __restrict__ wp)
{
    int mat   = blockIdx.x >> 4;
    int chunk = blockIdx.x & 15;
    const float* W = (mat == 0) ? wq : (mat == 1) ? wk : (mat == 2) ? wv : wp;
    uint32_t* dst = g_wt + mat * 8192;
    #pragma unroll
    for (int it = 0; it < 4; ++it) {
        int i = chunk * 512 + it * 128 + threadIdx.x;
        int k2 = i >> 7, n = i & 127;
        dst[n * 64 + k2] = packbf(W[(2 * k2) * 128 + n], W[(2 * k2 + 1) * 128 + n]);
    }
}

// ---------------------------------------------------------------------------
// Kernel 1: fold + LayerNorm + projection GEMM (R10's exact inner loops),
// 2 tiles of 64 rows per CTA so Wt is loaded ONCE per 128 rows.
// grid = (384, 3), block = 256 (8 warps).
// ---------------------------------------------------------------------------
#define XS_WSTR 68
#define XS_BSTR 272
#define WT_WOFF (64 * XS_WSTR)
#define WT_BOFF (64 * XS_BSTR)
#define K1_SMEM ((64 + 128) * XS_BSTR)

__global__ __launch_bounds__(256, 3) void ln_proj_mma(
    const float* __restrict__ q, const float* __restrict__ k, const float* __restrict__ v,
    const float* __restrict__ lnq_g, const float* __restrict__ lnq_b,
    const float* __restrict__ lnk_g, const float* __restrict__ lnk_b,
    const float* __restrict__ lnv_g, const float* __restrict__ lnv_b,
    const float* __restrict__ bq, const float* __restrict__ bk,
    const float* __restrict__ bv)
{
    extern __shared__ uint32_t smw[];
    uint32_t sbase = (uint32_t)__cvta_generic_to_shared(smw);

    const float* src; const float* gam; const float* bet;
    const float* bias; uint32_t* dst;
    int mat = blockIdx.y;
    if (mat == 0)      { src = q; gam = lnq_g; bet = lnq_b; bias = bq; dst = g_qp; }
    else if (mat == 1) { src = k; gam = lnk_g; bet = lnk_b; bias = bk; dst = g_kp; }
    else               { src = v; gam = lnv_g; bet = lnv_b; bias = bv; dst = g_vp; }
    const float qmul = (mat == 0) ? QSCALE : 1.0f;

    int tid  = threadIdx.x;
    int warp = tid >> 5;
    int lane = tid & 31;

    // Wt fill once per CTA
    {
        const uint4* wsrc = (const uint4*)(g_wt + mat * 8192);
        #pragma unroll
        for (int it = 0; it < 8; ++it) {
            int j  = it * 256 + tid;
            int n  = j >> 4, c4 = j & 15;
            *(uint4*)(smw + WT_WOFF + n * XS_WSTR + c4 * 4) = wsrc[j];
        }
    }

    float4 gg  = ((const float4*)gam)[lane];
    float4 bb4 = ((const float4*)bet)[lane];

    int mg = warp >> 2, ng = warp & 3;
    int g  = lane >> 2, c = lane & 3;
    int khi = (lane & 16) >> 1;
    uint32_t aA0 = sbase + (mg * 32 + (lane & 15)) * XS_BSTR + khi * 2;
    uint32_t aA1 = aA0 + 16 * XS_BSTR;
    uint32_t aB0 = sbase + WT_BOFF
                 + (ng * 32 + (lane & 7) + khi) * XS_BSTR + (lane & 8) * 2;
    uint32_t aB1 = aB0 + 16 * XS_BSTR;

    #pragma unroll
    for (int sub = 0; sub < 2; ++sub) {
        int row0 = blockIdx.x * 128 + sub * 64;

        // Hoisted fold decode: 64-token tile = fixed (b,l,n), contiguous rows
        int bIdx = row0 / (LWIN * QTOK);
        int rem  = row0 % (LWIN * QTOK);
        int l = rem / QTOK;
        int t = rem % QTOK;
        int nv = t >> 6;
        int x = l >> 3, y = l & 7;
        const float* srcBase = src +
            (size_t)((((bIdx * NVIEW + nv) * XD + x) * YD + y)) * (W1D * W2D * DIM);

        // Guard Xs overwrite vs prior iteration's ldsm reads (and order Wt fill)
        __syncthreads();

        // Phase A (R10 exact): warp per token, LN normalize, bf16 store
        #pragma unroll
        for (int it = 0; it < 8; ++it) {
            int rloc = it * 8 + warp;
            float4 xv = ((const float4*)(srcBase + rloc * DIM))[lane];
            float s  = xv.x + xv.y + xv.z + xv.w;
            float ss = xv.x * xv.x + xv.y * xv.y + xv.z * xv.z + xv.w * xv.w;
            #pragma unroll
            for (int o = 16; o; o >>= 1) {
                s  += __shfl_xor_sync(FULLMASK, s,  o);
                ss += __shfl_xor_sync(FULLMASK, ss, o);
            }
            float mu  = s * (1.0f / 128.0f);
            float var = ss * (1.0f / 128.0f) - mu * mu;
            float rs  = rsqrtf(var + EPS);
            float o0 = (xv.x - mu) * rs * gg.x + bb4.x;
            float o1 = (xv.y - mu) * rs * gg.y + bb4.y;
            float o2 = (xv.z - mu) * rs * gg.z + bb4.z;
            float o3 = (xv.w - mu) * rs * gg.w + bb4.w;
            smw[rloc * XS_WSTR + lane * 2    ] = packbf(o0, o1);
            smw[rloc * XS_WSTR + lane * 2 + 1] = packbf(o2, o3);
        }
        __syncthreads();

        // GEMM (R10 exact)
        float acc[2][4][4];
        #pragma unroll
        for (int mt = 0; mt < 2; ++mt)
            #pragma unroll
            for (int nt = 0; nt < 4; ++nt)
                { acc[mt][nt][0]=0.f; acc[mt][nt][1]=0.f; acc[mt][nt][2]=0.f; acc[mt][nt][3]=0.f; }

        #pragma unroll
        for (int kst = 0; kst < 8; ++kst) {
            uint32_t a0[4], a1[4], b0[4], b1[4];
            ldsm4(a0, aA0 + kst * 32);
            ldsm4(a1, aA1 + kst * 32);
            ldsm4(b0, aB0 + kst * 32);
            ldsm4(b1, aB1 + kst * 32);
            mma16(acc[0][0], a0, b0);     mma16(acc[0][1], a0, b0 + 2);
            mma16(acc[0][2], a0, b1);     mma16(acc[0][3], a0, b1 + 2);
            mma16(acc[1][0], a1, b0);     mma16(acc[1][1], a1, b0 + 2);
            mma16(acc[1][2], a1, b1);     mma16(acc[1][3], a1, b1 + 2);
        }

        // Epilogue (R10 exact): + bias, *qmul (q only), pack bf16, store
        #pragma unroll
        for (int nt = 0; nt < 4; ++nt) {
            int col = ng * 32 + nt * 8 + c * 2;
            float2 bv2 = *(const float2*)(bias + col);
            int wcol = ng * 16 + nt * 4 + c;
            #pragma unroll
            for (int mt = 0; mt < 2; ++mt) {
                int rr = row0 + mg * 32 + mt * 16 + g;
                dst[(size_t)rr * 64 + wcol] =
                    packbf((acc[mt][nt][0] + bv2.x) * qmul, (acc[mt][nt][1] + bv2.y) * qmul);
                dst[(size_t)(rr + 8) * 64 + wcol] =
                    packbf((acc[mt][nt][2] + bv2.x) * qmul, (acc[mt][nt][3] + bv2.y) * qmul);
            }
        }
    }
}

// ---------------------------------------------------------------------------
// Kernel 2: flash attention (R10 exact). One CTA per (b,l,head).
// ---------------------------------------------------------------------------
#define KS_WSTR 20
#define KS_BSTR 80
#define VT_WOFF (QTOK * KS_WSTR)
#define VT_BOFF (QTOK * KS_BSTR)
#define VT_WSTR 196
#define VT_BSTR 784
#define K2_SMEM (VT_BOFF + 32 * VT_BSTR)

__global__ __launch_bounds__(768, 1) void attn_mma()
{
    extern __shared__ uint32_t smw[];
    uint32_t sbase = (uint32_t)__cvta_generic_to_shared(smw);

    int bx = blockIdx.x;
    int bl = bx >> 2;
    int m  = bx & 3;
    size_t base_w = (size_t)bl * QTOK * 64 + m * 16;

    int tid = threadIdx.x, warp = tid >> 5, lane = tid & 31;
    int g = lane >> 2, c = lane & 3;

    #pragma unroll
    for (int it = 0; it < 2; ++it) {
        int i = it * 768 + tid;
        int row = i >> 2, c4 = i & 3;
        uint4 u = ((const uint4*)(g_kp + base_w + (size_t)row * 64))[c4];
        *(uint4*)(smw + row * KS_WSTR + c4 * 4) = u;
    }
    {
        int i = tid;
        int r2 = i >> 2, c4 = i & 3;
        uint4 u0 = ((const uint4*)(g_vp + base_w + (size_t)(2 * r2)     * 64))[c4];
        uint4 u1 = ((const uint4*)(g_vp + base_w + (size_t)(2 * r2 + 1) * 64))[c4];
        int w0 = c4 * 4;
        smw[VT_WOFF + (2*w0    ) * VT_WSTR + r2] = __byte_perm(u0.x, u1.x, 0x5410);
        smw[VT_WOFF + (2*w0 + 1) * VT_WSTR + r2] = __byte_perm(u0.x, u1.x, 0x7632);
        smw[VT_WOFF + (2*w0 + 2) * VT_WSTR + r2] = __byte_perm(u0.y, u1.y, 0x5410);
        smw[VT_WOFF + (2*w0 + 3) * VT_WSTR + r2] = __byte_perm(u0.y, u1.y, 0x7632);
        smw[VT_WOFF + (2*w0 + 4) * VT_WSTR + r2] = __byte_perm(u0.z, u1.z, 0x5410);
        smw[VT_WOFF + (2*w0 + 5) * VT_WSTR + r2] = __byte_perm(u0.z, u1.z, 0x7632);
        smw[VT_WOFF + (2*w0 + 6) * VT_WSTR + r2] = __byte_perm(u0.w, u1.w, 0x5410);
        smw[VT_WOFF + (2*w0 + 7) * VT_WSTR + r2] = __byte_perm(u0.w, u1.w, 0x7632);
    }

    int q0 = warp * 16;
    uint32_t qa[2][4];
    {
        const uint32_t* qr0 = g_qp + base_w + (size_t)(q0 + g) * 64;
        const uint32_t* qr1 = g_qp + base_w + (size_t)(q0 + g + 8) * 64;
        #pragma unroll
        for (int kst = 0; kst < 2; ++kst) {
            qa[kst][0] = qr0[kst * 8 + c    ];
            qa[kst][1] = qr1[kst * 8 + c    ];
            qa[kst][2] = qr0[kst * 8 + c + 4];
            qa[kst][3] = qr1[kst * 8 + c + 4];
        }
    }
    __syncthreads();

    float o[4][4];
    #pragma unroll
    for (int nt = 0; nt < 4; ++nt)
        { o[nt][0]=0.f; o[nt][1]=0.f; o[nt][2]=0.f; o[nt][3]=0.f; }
    float lp0 = 0.f, lp1 = 0.f;

    int rhi = (lane & 16) >> 1;
    uint32_t aK = sbase + ((lane & 7) + rhi) * KS_BSTR + (lane & 8) * 2;
    uint32_t aV = sbase + VT_BOFF + ((lane & 7) + rhi) * VT_BSTR + (lane & 8) * 2;

    for (int kc = 0; kc < QTOK; kc += 32) {
        float s[4][4];
        #pragma unroll
        for (int nt = 0; nt < 4; ++nt)
            { s[nt][0]=0.f; s[nt][1]=0.f; s[nt][2]=0.f; s[nt][3]=0.f; }

        #pragma unroll
        for (int kst = 0; kst < 2; ++kst) {
            uint32_t b0[4], b1[4];
            ldsm4(b0, aK + (kc)      * KS_BSTR + kst * 32);
            ldsm4(b1, aK + (kc + 16) * KS_BSTR + kst * 32);
            mma16(s[0], qa[kst], b0);     mma16(s[1], qa[kst], b0 + 2);
            mma16(s[2], qa[kst], b1);     mma16(s[3], qa[kst], b1 + 2);
        }

        #pragma unroll
        for (int nt = 0; nt < 4; ++nt) {
            s[nt][0] = exp2f(s[nt][0]);
            s[nt][1] = exp2f(s[nt][1]);
            s[nt][2] = exp2f(s[nt][2]);
            s[nt][3] = exp2f(s[nt][3]);
            lp0 += s[nt][0] + s[nt][1];
            lp1 += s[nt][2] + s[nt][3];
        }

        #pragma unroll
        for (int kt = 0; kt < 2; ++kt) {
            uint32_t pa[4];
            pa[0] = packbf(s[2*kt  ][0], s[2*kt  ][1]);
            pa[1] = packbf(s[2*kt  ][2], s[2*kt  ][3]);
            pa[2] = packbf(s[2*kt+1][0], s[2*kt+1][1]);
            pa[3] = packbf(s[2*kt+1][2], s[2*kt+1][3]);
            int kbase = kc + kt * 16;
            uint32_t v0[4], v1[4];
            ldsm4(v0, aV                + kbase * 2);
            ldsm4(v1, aV + 16 * VT_BSTR + kbase * 2);
            mma16(o[0], pa, v0);     mma16(o[1], pa, v0 + 2);
            mma16(o[2], pa, v1);     mma16(o[3], pa, v1 + 2);
        }
    }

    lp0 += __shfl_xor_sync(FULLMASK, lp0, 1);
    lp0 += __shfl_xor_sync(FULLMASK, lp0, 2);
    lp1 += __shfl_xor_sync(FULLMASK, lp1, 1);
    lp1 += __shfl_xor_sync(FULLMASK, lp1, 2);

    float inv0 = 1.0f / lp0;
    float inv1 = 1.0f / lp1;
    int r0 = q0 + g;
    #pragma unroll
    for (int nt = 0; nt < 4; ++nt) {
        int wcol = nt * 4 + c;
        g_at[base_w + (size_t)r0 * 64 + wcol]       = packbf(o[nt][0] * inv0, o[nt][1] * inv0);
        g_at[base_w + (size_t)(r0 + 8) * 64 + wcol] = packbf(o[nt][2] * inv1, o[nt][3] * inv1);
    }
}

// ---------------------------------------------------------------------------
// Kernel 3: mean-over-views + output projection (bf16 mma) + bias + skip.
// R8's measured-best config: 32-row tiles, grid=256, block=128.
// ---------------------------------------------------------------------------
#define WT3_WOFF (32 * XS_WSTR)
#define WT3_BOFF (32 * XS_BSTR)
#define K3_SMEM ((32 + 128) * XS_BSTR)

__global__ __launch_bounds__(128) void out_proj_mma(
    const float* __restrict__ bp,
    const float* __restrict__ skip, float* __restrict__ out)
{
    extern __shared__ uint32_t smw[];
    uint32_t sbase = (uint32_t)__cvta_generic_to_shared(smw);

    int tid  = threadIdx.x;
    int warp = tid >> 5;
    int lane = tid & 31;
    int row0 = blockIdx.x * 32;

    {
        const uint4* wsrc = (const uint4*)(g_wt + 3 * 8192);
        #pragma unroll
        for (int it = 0; it < 16; ++it) {
            int j  = it * 128 + tid;
            int n  = j >> 4, c4 = j & 15;
            *(uint4*)(smw + WT3_WOFF + n * XS_WSTR + c4 * 4) = wsrc[j];
        }
    }

    // Xs = mean over n, uint4 loads
    #pragma unroll
    for (int it = 0; it < 4; ++it) {
        int i = it * 128 + tid;
        int rloc = i >> 4, c4 = i & 15;
        int r2 = row0 + rloc;
        int bl = r2 >> 6;
        int wr = r2 & 63;
        const uint4* srcp = (const uint4*)(g_at + (size_t)(bl * QTOK + wr) * 64) + c4;
        float a0=0.f,a1=0.f,a2=0.f,a3=0.f,a4=0.f,a5=0.f,a6=0.f,a7=0.f;
        #pragma unroll
        for (int n = 0; n < NVIEW; ++n) {
            uint4 u = srcp[n * 64 * 16];
            a0 += bflo(u.x); a1 += bfhi(u.x);
            a2 += bflo(u.y); a3 += bfhi(u.y);
            a4 += bflo(u.z); a5 += bfhi(u.z);
            a6 += bflo(u.w); a7 += bfhi(u.w);
        }
        const float iv = 1.0f / 6.0f;
        uint4 ov;
        ov.x = packbf(a0 * iv, a1 * iv);
        ov.y = packbf(a2 * iv, a3 * iv);
        ov.z = packbf(a4 * iv, a5 * iv);
        ov.w = packbf(a6 * iv, a7 * iv);
        *(uint4*)(smw + rloc * XS_WSTR + c4 * 4) = ov;
    }
    __syncthreads();

    int ng = warp;
    int g  = lane >> 2, c = lane & 3;

    float acc[2][4][4];
    #pragma unroll
    for (int mt = 0; mt < 2; ++mt)
        #pragma unroll
        for (int nt = 0; nt < 4; ++nt)
            { acc[mt][nt][0]=0.f; acc[mt][nt][1]=0.f; acc[mt][nt][2]=0.f; acc[mt][nt][3]=0.f; }

    int khi = (lane & 16) >> 1;
    uint32_t aA0 = sbase + (lane & 15) * XS_BSTR + khi * 2;
    uint32_t aA1 = aA0 + 16 * XS_BSTR;
    uint32_t aB0 = sbase + WT3_BOFF
                 + (ng * 32 + (lane & 7) + khi) * XS_BSTR + (lane & 8) * 2;
    uint32_t aB1 = aB0 + 16 * XS_BSTR;

    #pragma unroll
    for (int kst = 0; kst < 8; ++kst) {
        uint32_t a0[4], a1[4], b0[4], b1[4];
        ldsm4(a0, aA0 + kst * 32);
        ldsm4(a1, aA1 + kst * 32);
        ldsm4(b0, aB0 + kst * 32);
        ldsm4(b1, aB1 + kst * 32);
        mma16(acc[0][0], a0, b0);     mma16(acc[0][1], a0, b0 + 2);
        mma16(acc[0][2], a0, b1);     mma16(acc[0][3], a0, b1 + 2);
        mma16(acc[1][0], a1, b0);     mma16(acc[1][1], a1, b0 + 2);
        mma16(acc[1][2], a1, b1);     mma16(acc[1][3], a1, b1 + 2);
    }

    #pragma unroll
    for (int nt = 0; nt < 4; ++nt) {
        int col = ng * 32 + nt * 8 + c * 2;
        float2 bv2 = *(const float2*)(bp + col);
        #pragma unroll
        for (int mt = 0; mt < 2; ++mt) {
            int rr = row0 + mt * 16 + g;
            float2 sk0 = *(const float2*)(skip + (size_t)rr * 128 + col);
            float2 sk1 = *(const float2*)(skip + (size_t)(rr + 8) * 128 + col);
            float2 o0 = { acc[mt][nt][0] + bv2.x + sk0.x, acc[mt][nt][1] + bv2.y + sk0.y };
            float2 o1 = { acc[mt][nt][2] + bv2.x + sk1.x, acc[mt][nt][3] + bv2.y + sk1.y };
            *(float2*)(out + (size_t)rr * 128 + col)       = o0;
            *(float2*)(out + (size_t)(rr + 8) * 128 + col) = o1;
        }
    }
}

// ---------------------------------------------------------------------------
extern "C" void kernel_launch(void* const* d_in, const int* in_sizes, int n_in,
                              void* d_out, int out_size)
{
    const float* q     = (const float*)d_in[0];
    const float* k     = (const float*)d_in[1];
    const float* v     = (const float*)d_in[2];
    const float* skip  = (const float*)d_in[3];
    const float* lnq_g = (const float*)d_in[4];
    const float* lnq_b = (const float*)d_in[5];
    const float* lnk_g = (const float*)d_in[6];
    const float* lnk_b = (const float*)d_in[7];
    const float* lnv_g = (const float*)d_in[8];
    const float* lnv_b = (const float*)d_in[9];
    const float* wq    = (const float*)d_in[10];
    const float* bq    = (const float*)d_in[11];
    const float* wk    = (const float*)d_in[12];
    const float* bk    = (const float*)d_in[13];
    const float* wv    = (const float*)d_in[14];
    const float* bv    = (const float*)d_in[15];
    const float* wp    = (const float*)d_in[16];
    const float* bp    = (const float*)d_in[17];
    float* out = (float*)d_out;

    cudaFuncSetAttribute(ln_proj_mma,  cudaFuncAttributeMaxDynamicSharedMemorySize, K1_SMEM);
    cudaFuncSetAttribute(attn_mma,     cudaFuncAttributeMaxDynamicSharedMemorySize, K2_SMEM);
    cudaFuncSetAttribute(out_proj_mma, cudaFuncAttributeMaxDynamicSharedMemorySize, K3_SMEM);

    pack_w_kernel<<<64, 128>>>(wq, wk, wv, wp);

    ln_proj_mma<<<dim3(TOKENS / 128, 3), 256, K1_SMEM>>>(
        q, k, v, lnq_g, lnq_b, lnk_g, lnk_b, lnv_g, lnv_b, bq, bk, bv);

    attn_mma<<<NBL * HEADS, 768, K2_SMEM>>>();

    out_proj_mma<<<R2ROWS / 32, 128, K3_SMEM>>>(bp, skip, out);
}